// round 4
// baseline (speedup 1.0000x reference)
#include <cuda_runtime.h>
#include <cstdint>

// Problem constants (fixed by reference setup_inputs)
#define B_SZ   16
#define T_IN   512
#define D_DIM  768
#define D4     (D_DIM / 4)     // 192 float4 per row

// Scratch: packed (start<<3 | dur) per phoneme, and total frames per batch.
__device__ int g_sd[B_SZ * T_IN];
__device__ int g_total[B_SZ];

// Kernel 1: per-batch inclusive scan of durations (warp-shuffle based),
// writes packed start/dur. One block per batch, 512 threads.
// durations are int32 on device (JAX default config downgrades int64).
__global__ void build_sd_kernel(const int* __restrict__ durations) {
    __shared__ int warp_sums[16];
    const int b    = blockIdx.x;
    const int tid  = threadIdx.x;
    const int lane = tid & 31;
    const int wid  = tid >> 5;

    const int dur = durations[b * T_IN + tid];

    // Intra-warp inclusive scan
    int v = dur;
    #pragma unroll
    for (int off = 1; off < 32; off <<= 1) {
        int n = __shfl_up_sync(0xFFFFFFFFu, v, off);
        if (lane >= off) v += n;
    }
    if (lane == 31) warp_sums[wid] = v;
    __syncthreads();

    // Warp 0 scans the 16 warp sums
    if (wid == 0) {
        int s = (lane < 16) ? warp_sums[lane] : 0;
        #pragma unroll
        for (int off = 1; off < 16; off <<= 1) {
            int n = __shfl_up_sync(0xFFFFFFFFu, s, off);
            if (lane >= off) s += n;
        }
        if (lane < 16) warp_sums[lane] = s;
    }
    __syncthreads();

    const int cum   = v + (wid > 0 ? warp_sums[wid - 1] : 0);
    const int start = cum - dur;
    g_sd[b * T_IN + tid] = (start << 3) | dur;     // start < 4096, dur < 8
    if (tid == T_IN - 1) g_total[b] = cum;
}

// Kernel 2: scatter. One block per (phoneme, batch); 192 threads = one float4
// per D-column. Load the row once, write it to its `dur` output frames, then
// zero this block's share of the padding tail.
__global__ void __launch_bounds__(D4) scatter_kernel(
    const float4* __restrict__ hidden, float4* __restrict__ out, int t_out) {
    const int i = blockIdx.x;
    const int b = blockIdx.y;
    const int d = threadIdx.x;

    // Row load depends only on blockIdx -> issues immediately,
    // overlapping the scalar start/dur load.
    const float4 v = __ldg(hidden + ((size_t)b * T_IN + i) * D4 + d);

    const int sd    = g_sd[b * T_IN + i];
    const int start = sd >> 3;
    const int dur   = sd & 7;

    float4* const out_b = out + (size_t)b * t_out * D4;

    // Scatter: dur consecutive frames, coalesced 768B stores per frame.
    float4* o = out_b + (size_t)start * D4 + d;
    #pragma unroll 4
    for (int k = 0; k < dur; ++k)
        o[(size_t)k * D4] = v;

    // Padding: frames [total, t_out) belong to no phoneme; block i zeros
    // frames total+i, total+i+512, ...
    const int total = g_total[b];
    const float4 z = make_float4(0.f, 0.f, 0.f, 0.f);
    for (int t = total + i; t < t_out; t += T_IN)
        out_b[(size_t)t * D4 + d] = z;
}

extern "C" void kernel_launch(void* const* d_in, const int* in_sizes, int n_in,
                              void* d_out, int out_size) {
    const float* hidden    = (const float*)d_in[0];  // (B, T_IN, D) f32
    const int*   durations = (const int*)d_in[1];    // (B, T_IN) int32

    const int t_out = out_size / (B_SZ * D_DIM);

    build_sd_kernel<<<B_SZ, T_IN>>>(durations);

    dim3 grid(T_IN, B_SZ);
    scatter_kernel<<<grid, D4>>>((const float4*)hidden, (float4*)d_out, t_out);
}

// round 5
// speedup vs baseline: 1.0878x; 1.0878x over previous
#include <cuda_runtime.h>
#include <cstdint>

// Problem constants (fixed by reference setup_inputs)
#define B_SZ   16
#define T_IN   512
#define D_DIM  768
#define D4     (D_DIM / 4)     // 192 float4 per row = blockDim
#define PH     4               // phonemes per block
#define NBLK   (T_IN / PH)     // 128 blocks per batch

// Single fused kernel: per-block redundant prefix-reduce of durations,
// then scatter PH input rows to their output frame ranges + padding zeros.
// durations are int32 on device (JAX default config downgrades int64).
__global__ void __launch_bounds__(D4) lr_fused_kernel(
    const float4* __restrict__ hidden,
    const int*    __restrict__ durations,
    float4*       __restrict__ out,
    int t_out) {
    __shared__ int sdur[T_IN];
    __shared__ int red_before[6], red_all[6];

    const int blk = blockIdx.x;         // 0..NBLK-1
    const int b   = blockIdx.y;
    const int i0  = blk * PH;
    const int tid = threadIdx.x;        // 0..191
    const int lane = tid & 31;
    const int wid  = tid >> 5;          // 0..5

    // ---- Phase 0: issue the PH row loads immediately (depend only on blockIdx) ----
    float4 v[PH];
    #pragma unroll
    for (int k = 0; k < PH; ++k)
        v[k] = __ldg(hidden + ((size_t)b * T_IN + i0 + k) * D4 + tid);

    // ---- Phase 1: load this batch's durations, accumulate prefix & total ----
    const int* durb = durations + b * T_IN;
    int before = 0, all = 0;
    #pragma unroll
    for (int j = tid; j < T_IN; j += D4) {   // 3 iterations (512/192 -> j<512)
        int dv = __ldg(durb + j);
        sdur[j] = dv;
        all += dv;
        if (j < i0) before += dv;
    }
    // warp reduce both accumulators
    #pragma unroll
    for (int off = 16; off > 0; off >>= 1) {
        before += __shfl_down_sync(0xFFFFFFFFu, before, off);
        all    += __shfl_down_sync(0xFFFFFFFFu, all, off);
    }
    if (lane == 0) { red_before[wid] = before; red_all[wid] = all; }
    __syncthreads();

    int base = 0, total = 0;
    #pragma unroll
    for (int w = 0; w < 6; ++w) { base += red_before[w]; total += red_all[w]; }

    // ---- Phase 2: scatter PH rows ----
    float4* const out_b = out + (size_t)b * t_out * D4;
    int run = base;
    #pragma unroll
    for (int k = 0; k < PH; ++k) {
        const int dur = sdur[i0 + k];
        float4* o = out_b + (size_t)run * D4 + tid;
        #pragma unroll 4
        for (int j = 0; j < dur; ++j)
            o[(size_t)j * D4] = v[k];
        run += dur;
    }

    // ---- Phase 3: padding frames [total, t_out), strided across blocks ----
    const float4 z = make_float4(0.f, 0.f, 0.f, 0.f);
    for (int t = total + blk; t < t_out; t += NBLK)
        out_b[(size_t)t * D4 + tid] = z;
}

extern "C" void kernel_launch(void* const* d_in, const int* in_sizes, int n_in,
                              void* d_out, int out_size) {
    const float* hidden    = (const float*)d_in[0];  // (B, T_IN, D) f32
    const int*   durations = (const int*)d_in[1];    // (B, T_IN) int32

    const int t_out = out_size / (B_SZ * D_DIM);

    dim3 grid(NBLK, B_SZ);
    lr_fused_kernel<<<grid, D4>>>((const float4*)hidden, durations,
                                  (float4*)d_out, t_out);
}